// round 6
// baseline (speedup 1.0000x reference)
#include <cuda_runtime.h>
#include <cuda_fp16.h>
#include <cstdint>

#define NROWS 8192
#define HDIM  4096
#define ODIM  4096
#define EEXP  4

#define BM 128
#define BN 128
#define BK 64
#define KT64 (HDIM / BK)      // 64 k-tiles
#define STAGES 3
#define AB_STAGE 32768        // A 16KB + B 16KB per stage
#define SM_OCS  (STAGES * AB_STAGE)          // 98304
#define SM_BIAS (SM_OCS + EEXP * BN * 4)     // + 2048
#define SMEM_TOTAL (SM_BIAS + BN * 4)        // + 512 = 100864 B

__device__ __align__(1024) __half g_xs[(size_t)NROWS * HDIM];     // x * in_scale, fp16
__device__ __align__(1024) __half g_bsgn[(size_t)ODIM * HDIM];    // sign(W), fp16
__device__ __align__(16)   float  g_rw[(size_t)NROWS * EEXP];     // routing weights

static __device__ __forceinline__ uint32_t smem_u32(const void* p) {
    uint32_t a;
    asm("{ .reg .u64 t; cvta.to.shared.u64 t, %1; cvt.u32.u64 %0, t; }" : "=r"(a) : "l"(p));
    return a;
}
static __device__ __forceinline__ void cp16(uint32_t dst, const void* src) {
    asm volatile("cp.async.cg.shared.global [%0], [%1], 16;" :: "r"(dst), "l"(src));
}
static __device__ __forceinline__ void cp_commit() {
    asm volatile("cp.async.commit_group;" ::: "memory");
}
template <int N> static __device__ __forceinline__ void cp_wait() {
    asm volatile("cp.async.wait_group %0;" :: "n"(N) : "memory");
}
static __device__ __forceinline__ void ldmx4(uint32_t* r, uint32_t addr) {
    asm volatile("ldmatrix.sync.aligned.m8n8.x4.shared.b16 {%0,%1,%2,%3}, [%4];"
                 : "=r"(r[0]), "=r"(r[1]), "=r"(r[2]), "=r"(r[3]) : "r"(addr));
}
static __device__ __forceinline__ void mma16816(float* d, const uint32_t* a, uint32_t b0, uint32_t b1) {
    asm volatile("mma.sync.aligned.m16n8k16.row.col.f32.f16.f16.f32 "
                 "{%0,%1,%2,%3}, {%4,%5,%6,%7}, {%8,%9}, {%0,%1,%2,%3};"
                 : "+f"(d[0]), "+f"(d[1]), "+f"(d[2]), "+f"(d[3])
                 : "r"(a[0]), "r"(a[1]), "r"(a[2]), "r"(a[3]), "r"(b0), "r"(b1));
}

// ---------------- K0: sign(W) -> fp16 ----------------
__global__ void __launch_bounds__(256) sign_kernel(const float4* __restrict__ w, __half2* __restrict__ bs) {
    size_t i = (size_t)blockIdx.x * 256 + threadIdx.x;
    float4 v = w[i];
    float s0 = (v.x > 0.f) ? 1.f : ((v.x < 0.f) ? -1.f : 0.f);
    float s1 = (v.y > 0.f) ? 1.f : ((v.y < 0.f) ? -1.f : 0.f);
    float s2 = (v.z > 0.f) ? 1.f : ((v.z < 0.f) ? -1.f : 0.f);
    float s3 = (v.w > 0.f) ? 1.f : ((v.w < 0.f) ? -1.f : 0.f);
    bs[2 * i]     = __floats2half2_rn(s0, s1);
    bs[2 * i + 1] = __floats2half2_rn(s2, s3);
}

// ---------------- K1: router + xs = x*in_scale (fp16) ----------------
__global__ void __launch_bounds__(256) router_kernel(
    const float* __restrict__ x, const float* __restrict__ gate_w,
    const float* __restrict__ ics, __half* __restrict__ xs, float* __restrict__ rw_out) {
    __shared__ float sx[HDIM];
    __shared__ float sred[8][4];
    __shared__ float srw[4];
    const int n = blockIdx.x;
    const int tid = threadIdx.x;
    const int lane = tid & 31, wid = tid >> 5;

    const float4* xrow = (const float4*)(x + (size_t)n * HDIM);
    float4* sx4 = (float4*)sx;
    for (int i = tid; i < HDIM / 4; i += 256) sx4[i] = xrow[i];
    __syncthreads();

    float a0 = 0.f, a1 = 0.f, a2 = 0.f, a3 = 0.f;
    for (int h = tid; h < HDIM; h += 256) {
        float xv = sx[h];
        a0 += xv * gate_w[h];
        a1 += xv * gate_w[HDIM + h];
        a2 += xv * gate_w[2 * HDIM + h];
        a3 += xv * gate_w[3 * HDIM + h];
    }
    #pragma unroll
    for (int off = 16; off; off >>= 1) {
        a0 += __shfl_xor_sync(0xFFFFFFFFu, a0, off);
        a1 += __shfl_xor_sync(0xFFFFFFFFu, a1, off);
        a2 += __shfl_xor_sync(0xFFFFFFFFu, a2, off);
        a3 += __shfl_xor_sync(0xFFFFFFFFu, a3, off);
    }
    if (lane == 0) { sred[wid][0] = a0; sred[wid][1] = a1; sred[wid][2] = a2; sred[wid][3] = a3; }
    __syncthreads();
    if (tid == 0) {
        float l0 = 0.f, l1 = 0.f, l2 = 0.f, l3 = 0.f;
        #pragma unroll
        for (int w = 0; w < 8; w++) { l0 += sred[w][0]; l1 += sred[w][1]; l2 += sred[w][2]; l3 += sred[w][3]; }
        float mx = fmaxf(fmaxf(l0, l1), fmaxf(l2, l3));
        float e0 = expf(l0 - mx), e1 = expf(l1 - mx), e2 = expf(l2 - mx), e3 = expf(l3 - mx);
        float inv = 1.f / (e0 + e1 + e2 + e3);
        srw[0] = e0 * inv; srw[1] = e1 * inv; srw[2] = e2 * inv; srw[3] = e3 * inv;
        rw_out[(size_t)n * 4 + 0] = srw[0]; rw_out[(size_t)n * 4 + 1] = srw[1];
        rw_out[(size_t)n * 4 + 2] = srw[2]; rw_out[(size_t)n * 4 + 3] = srw[3];
    }
    __syncthreads();
    const float r0 = srw[0], r1 = srw[1], r2 = srw[2], r3 = srw[3];
    __half* xo = xs + (size_t)n * HDIM;
    for (int h = tid * 2; h < HDIM; h += 512) {
        float2 i0 = *(const float2*)(ics + h);
        float2 i1 = *(const float2*)(ics + HDIM + h);
        float2 i2 = *(const float2*)(ics + 2 * HDIM + h);
        float2 i3 = *(const float2*)(ics + 3 * HDIM + h);
        float s0 = r0 * i0.x + r1 * i1.x + r2 * i2.x + r3 * i3.x;
        float s1 = r0 * i0.y + r1 * i1.y + r2 * i2.y + r3 * i3.y;
        *(__half2*)(xo + h) = __floats2half2_rn(sx[h] * s0, sx[h + 1] * s1);
    }
}

// ---------------- K2: HMMA (mma.sync) GEMM + fused epilogue ----------------
// D[m, o] = sum_k XS[m,k] * BSGN[o,k]; out = D * (rw . ocs[:,o]) + bias[o]
static __device__ __forceinline__ void load_stage(uint32_t sbase, int s, int kt,
                                                  int m0, int n0, int tid) {
    const uint32_t sA = sbase + s * AB_STAGE;
    const uint32_t sB = sA + 16384;
    const __half* gA = g_xs   + (size_t)m0 * HDIM + kt * BK;
    const __half* gB = g_bsgn + (size_t)n0 * HDIM + kt * BK;
    #pragma unroll
    for (int i = 0; i < 4; i++) {
        int l = tid + i * 256;                 // 1024 16B-chunks per tile
        int row = l >> 3, c = l & 7;
        uint32_t sw = (uint32_t)((c ^ (row & 7)) << 4);
        cp16(sA + row * 128 + sw, gA + (size_t)row * HDIM + c * 8);
    }
    #pragma unroll
    for (int i = 0; i < 4; i++) {
        int l = tid + i * 256;
        int row = l >> 3, c = l & 7;
        uint32_t sw = (uint32_t)((c ^ (row & 7)) << 4);
        cp16(sB + row * 128 + sw, gB + (size_t)row * HDIM + c * 8);
    }
}

__global__ void __launch_bounds__(256, 2) gemm_kernel(
    const float* __restrict__ rw,
    const float* __restrict__ ocs,
    const float* __restrict__ bias,
    float* __restrict__ out) {
    extern __shared__ __align__(128) uint8_t smem[];
    const uint32_t sbase = smem_u32(smem);
    const int tid  = threadIdx.x;
    const int lane = tid & 31;
    const int w    = tid >> 5;
    const int wm   = w >> 2;          // 0..1 -> m offset 64*wm
    const int wn   = w & 3;           // 0..3 -> n offset 32*wn
    const int m0   = blockIdx.y * BM;
    const int n0   = blockIdx.x * BN;

    float* s_ocs  = (float*)(smem + SM_OCS);
    float* s_bias = (float*)(smem + SM_BIAS);
    for (int i = tid; i < EEXP * BN; i += 256) s_ocs[i] = ocs[(size_t)(i >> 7) * ODIM + n0 + (i & (BN - 1))];
    for (int i = tid; i < BN; i += 256) s_bias[i] = bias[n0 + i];

    float acc[4][4][4];
    #pragma unroll
    for (int a = 0; a < 4; a++)
        #pragma unroll
        for (int b = 0; b < 4; b++)
            #pragma unroll
            for (int c = 0; c < 4; c++) acc[a][b][c] = 0.f;

    // prologue: STAGES-1 stages in flight
    #pragma unroll
    for (int s = 0; s < STAGES - 1; s++) { load_stage(sbase, s, s, m0, n0, tid); cp_commit(); }

    const int lr = lane & 15;         // row within 16-row frag
    const int lc = lane >> 4;         // 0/1 -> left/right 8-col chunk
    const int sw = lane & 7;          // swizzle xor term

    for (int kt = 0; kt < KT64; kt++) {
        cp_wait<STAGES - 2>();
        __syncthreads();
        int nk = kt + STAGES - 1;
        if (nk < KT64) load_stage(sbase, nk % STAGES, nk, m0, n0, tid);
        cp_commit();

        const int s = kt % STAGES;
        const uint32_t sA = sbase + s * AB_STAGE + (wm * 64) * 128;
        const uint32_t sB = sbase + s * AB_STAGE + 16384 + (wn * 32) * 128;

        #pragma unroll
        for (int kk = 0; kk < 4; kk++) {
            uint32_t a[4][4];
            #pragma unroll
            for (int mi = 0; mi < 4; mi++)
                ldmx4(a[mi], sA + (mi * 16 + lr) * 128 + (uint32_t)(((kk * 2 + lc) ^ sw) << 4));
            uint32_t b[2][4];
            #pragma unroll
            for (int nj = 0; nj < 2; nj++)
                ldmx4(b[nj], sB + (nj * 16 + lr) * 128 + (uint32_t)(((kk * 2 + lc) ^ sw) << 4));
            #pragma unroll
            for (int mi = 0; mi < 4; mi++)
                #pragma unroll
                for (int ni = 0; ni < 4; ni++)
                    mma16816(acc[mi][ni], a[mi], b[ni >> 1][ni & 1], b[ni >> 1][(ni & 1) + 2]);
        }
    }

    // -------- epilogue --------
    const int q = lane >> 2;          // 0..7 row-in-8
    const int p = (lane & 3) * 2;     // col pair base
    #pragma unroll
    for (int mi = 0; mi < 4; mi++) {
        const int r0 = m0 + wm * 64 + mi * 16 + q;
        const float4 w0 = *(const float4*)(rw + (size_t)r0 * 4);
        const float4 w1 = *(const float4*)(rw + (size_t)(r0 + 8) * 4);
        float* o0 = out + (size_t)r0 * ODIM + n0 + wn * 32;
        float* o1 = o0 + (size_t)8 * ODIM;
        #pragma unroll
        for (int ni = 0; ni < 4; ni++) {
            const int c  = ni * 8 + p;
            const int cg = wn * 32 + c;
            const float oa0 = s_ocs[cg],          oa1 = s_ocs[cg + 1];
            const float ob0 = s_ocs[BN + cg],     ob1 = s_ocs[BN + cg + 1];
            const float oc0 = s_ocs[2 * BN + cg], oc1 = s_ocs[2 * BN + cg + 1];
            const float od0 = s_ocs[3 * BN + cg], od1 = s_ocs[3 * BN + cg + 1];
            const float bz0 = s_bias[cg], bz1 = s_bias[cg + 1];
            const float s00 = w0.x * oa0 + w0.y * ob0 + w0.z * oc0 + w0.w * od0;
            const float s01 = w0.x * oa1 + w0.y * ob1 + w0.z * oc1 + w0.w * od1;
            const float s10 = w1.x * oa0 + w1.y * ob0 + w1.z * oc0 + w1.w * od0;
            const float s11 = w1.x * oa1 + w1.y * ob1 + w1.z * oc1 + w1.w * od1;
            float2 v0, v1;
            v0.x = acc[mi][ni][0] * s00 + bz0;
            v0.y = acc[mi][ni][1] * s01 + bz1;
            v1.x = acc[mi][ni][2] * s10 + bz0;
            v1.y = acc[mi][ni][3] * s11 + bz1;
            *(float2*)(o0 + c) = v0;
            *(float2*)(o1 + c) = v1;
        }
    }
}

// ---------------- host ----------------
extern "C" void kernel_launch(void* const* d_in, const int* in_sizes, int n_in,
                              void* d_out, int out_size) {
    const float* x      = (const float*)d_in[0];
    const float* w      = (const float*)d_in[1];
    const float* bias   = (const float*)d_in[2];
    const float* gate_w = (const float*)d_in[3];
    const float* ics    = (const float*)d_in[4];
    const float* ocs    = (const float*)d_in[5];
    float* out = (float*)d_out;
    (void)in_sizes; (void)n_in; (void)out_size;

    void *p_xs = 0, *p_bs = 0, *p_rw = 0;
    cudaGetSymbolAddress(&p_xs, g_xs);
    cudaGetSymbolAddress(&p_bs, g_bsgn);
    cudaGetSymbolAddress(&p_rw, g_rw);
    if (!p_xs || !p_bs || !p_rw) return;

    sign_kernel<<<(ODIM * (size_t)HDIM / 4) / 256, 256>>>((const float4*)w, (__half2*)p_bs);
    router_kernel<<<NROWS, 256>>>(x, gate_w, ics, (__half*)p_xs, (float*)p_rw);

    static int smem_set = 0;
    if (!smem_set) {
        cudaFuncSetAttribute(gemm_kernel, cudaFuncAttributeMaxDynamicSharedMemorySize, SMEM_TOTAL);
        smem_set = 1;
    }
    dim3 grid(ODIM / BN, NROWS / BM);
    gemm_kernel<<<grid, 256, SMEM_TOTAL>>>((const float*)p_rw, ocs, bias, out);
}